// round 2
// baseline (speedup 1.0000x reference)
#include <cuda_runtime.h>

#define N_NODES  50000
#define N_EDGES  800000
#define HID      128
#define N_GRAPHS 512

// ---------------- scratch (static __device__ — no allocations allowed) ----------------
__device__ int   g_deg[N_NODES];
__device__ int   g_cursor[N_NODES];
__device__ int   g_row_start[N_NODES + 1];
__device__ int   g_counts[N_GRAPHS];
__device__ int   g_csr_src[N_EDGES];
__device__ float g_inv_deg[N_NODES];
__device__ float g_y[(size_t)N_NODES * 256];   // [node][0:128)=h@Wl^T, [128:256)=h@Wr^T
__device__ float g_h0[(size_t)N_NODES * HID];
__device__ float g_h1[(size_t)N_NODES * HID];

// ---------------- f32x2 packed-FMA helpers (FFMA2) ----------------
__device__ __forceinline__ unsigned long long f2pk(float x, float y) {
    unsigned long long r;
    asm("mov.b64 %0, {%1, %2};" : "=l"(r) : "f"(x), "f"(y));
    return r;
}
__device__ __forceinline__ void f2fma(unsigned long long& d, unsigned long long a, unsigned long long b) {
    asm("fma.rn.f32x2 %0, %1, %2, %0;" : "+l"(d) : "l"(a), "l"(b));
}
__device__ __forceinline__ float2 f2unpk(unsigned long long v) {
    float2 r;
    asm("mov.b64 {%0, %1}, %2;" : "=f"(r.x), "=f"(r.y) : "l"(v));
    return r;
}

// ---------------- init: zero deg/counts/pooled ----------------
__global__ void init_kernel(float* __restrict__ pooled) {
    int i = blockIdx.x * blockDim.x + threadIdx.x;
    int stride = gridDim.x * blockDim.x;
    for (int j = i; j < N_NODES; j += stride) g_deg[j] = 0;
    for (int j = i; j < N_GRAPHS; j += stride) g_counts[j] = 0;
    for (int j = i; j < N_GRAPHS * HID; j += stride) pooled[j] = 0.0f;
}

// ---------------- histograms: in-degree + per-graph node counts (int32 inputs!) ----------------
__global__ void hist_kernel(const int* __restrict__ ei, const int* __restrict__ batch) {
    int e = blockIdx.x * blockDim.x + threadIdx.x;
    if (e < N_EDGES) atomicAdd(&g_deg[ei[N_EDGES + e]], 1);
    if (e < N_NODES) atomicAdd(&g_counts[batch[e]], 1);
}

// ---------------- single-block exclusive scan over deg -> row_start, cursor, inv_deg ----------------
__global__ void scan_kernel() {
    __shared__ int warp_sums[32];
    __shared__ int s_carry;
    const int t = threadIdx.x;
    const int lane = t & 31, wid = t >> 5;
    if (t == 0) s_carry = 0;
    __syncthreads();
    for (int base = 0; base < N_NODES; base += 1024) {
        int i = base + t;
        int v = (i < N_NODES) ? g_deg[i] : 0;
        int x = v;
#pragma unroll
        for (int o = 1; o < 32; o <<= 1) {
            int y = __shfl_up_sync(0xffffffffu, x, o);
            if (lane >= o) x += y;
        }
        if (lane == 31) warp_sums[wid] = x;
        __syncthreads();
        if (wid == 0) {
            int w = warp_sums[lane];
#pragma unroll
            for (int o = 1; o < 32; o <<= 1) {
                int y = __shfl_up_sync(0xffffffffu, w, o);
                if (lane >= o) w += y;
            }
            warp_sums[lane] = w;
        }
        __syncthreads();
        int prefix = s_carry + (wid ? warp_sums[wid - 1] : 0) + (x - v);
        if (i < N_NODES) {
            g_row_start[i] = prefix;
            g_cursor[i]    = prefix;
            g_inv_deg[i]   = 1.0f / fmaxf((float)v, 1.0f);
        }
        __syncthreads();
        if (t == 0) s_carry += warp_sums[31];
        __syncthreads();
    }
    if (t == 0) g_row_start[N_NODES] = s_carry;
}

// ---------------- CSR fill: edges bucketed by dst ----------------
__global__ void csr_kernel(const int* __restrict__ ei) {
    int e = blockIdx.x * blockDim.x + threadIdx.x;
    if (e >= N_EDGES) return;
    int d = ei[N_EDGES + e];
    int p = atomicAdd(&g_cursor[d], 1);
    g_csr_src[p] = ei[e];
}

// ---------------- GEMM: Y[:, by*128 : by*128+128] = A(50000x128) @ W^T (W is 128x128 row-major) ----------------
// grid = (ceil(N/128), 2), block = 256, dynamic smem = 128*132*4 + 2*8*132*4
__global__ __launch_bounds__(256, 2)
void gemm_kernel(const float* __restrict__ A, const float* __restrict__ Wl,
                 const float* __restrict__ Wr, float* __restrict__ Y) {
    extern __shared__ float sm[];
    float(*Ws)[132] = reinterpret_cast<float(*)[132]>(sm);            // Ws[k][j]
    float(*As)[8][132] = reinterpret_cast<float(*)[8][132]>(sm + 128 * 132);  // As[buf][kk][r]

    const float* W = (blockIdx.y == 0) ? Wl : Wr;
    const int row0 = blockIdx.x * 128;
    const int colOff = blockIdx.y * 128;
    const int t = threadIdx.x;
    const int r0 = (t >> 4) * 8;
    const int c0 = (t & 15) * 8;

    // load W transposed into smem: W[j*128+k] -> Ws[k][j]
    for (int idx = t; idx < 128 * 128; idx += 256) {
        int j = idx >> 7, k = idx & 127;
        Ws[k][j] = W[idx];
    }

    unsigned long long acc[8][4];
#pragma unroll
    for (int i = 0; i < 8; i++)
#pragma unroll
        for (int j = 0; j < 4; j++) acc[i][j] = f2pk(0.0f, 0.0f);

    const int rA = t >> 1;
    const int hA = (t & 1) * 4;
    const int rowA = row0 + rA;

    // preload chunk 0
    {
        float4 v = make_float4(0, 0, 0, 0);
        if (rowA < N_NODES) v = *reinterpret_cast<const float4*>(&A[rowA * HID + 0 + hA]);
        As[0][hA + 0][rA] = v.x; As[0][hA + 1][rA] = v.y;
        As[0][hA + 2][rA] = v.z; As[0][hA + 3][rA] = v.w;
    }
    __syncthreads();

    for (int c = 0; c < 16; c++) {
        const int buf = c & 1;
        if (c < 15) {
            float4 v = make_float4(0, 0, 0, 0);
            if (rowA < N_NODES) v = *reinterpret_cast<const float4*>(&A[rowA * HID + (c + 1) * 8 + hA]);
            As[buf ^ 1][hA + 0][rA] = v.x; As[buf ^ 1][hA + 1][rA] = v.y;
            As[buf ^ 1][hA + 2][rA] = v.z; As[buf ^ 1][hA + 3][rA] = v.w;
        }
#pragma unroll
        for (int kk = 0; kk < 8; kk++) {
            const int k = c * 8 + kk;
            float4 a0 = *reinterpret_cast<const float4*>(&As[buf][kk][r0]);
            float4 a1 = *reinterpret_cast<const float4*>(&As[buf][kk][r0 + 4]);
            float4 b0 = *reinterpret_cast<const float4*>(&Ws[k][c0]);
            float4 b1 = *reinterpret_cast<const float4*>(&Ws[k][c0 + 4]);
            unsigned long long bp[4] = {f2pk(b0.x, b0.y), f2pk(b0.z, b0.w),
                                        f2pk(b1.x, b1.y), f2pk(b1.z, b1.w)};
            float ar[8] = {a0.x, a0.y, a0.z, a0.w, a1.x, a1.y, a1.z, a1.w};
#pragma unroll
            for (int rr = 0; rr < 8; rr++) {
                unsigned long long ad = f2pk(ar[rr], ar[rr]);
#pragma unroll
                for (int cc = 0; cc < 4; cc++) f2fma(acc[rr][cc], ad, bp[cc]);
            }
        }
        __syncthreads();
    }

#pragma unroll
    for (int rr = 0; rr < 8; rr++) {
        int row = row0 + r0 + rr;
        if (row < N_NODES) {
            float2 p0 = f2unpk(acc[rr][0]), p1 = f2unpk(acc[rr][1]);
            float2 p2 = f2unpk(acc[rr][2]), p3 = f2unpk(acc[rr][3]);
            float4 o0 = make_float4(p0.x, p0.y, p1.x, p1.y);
            float4 o1 = make_float4(p2.x, p2.y, p3.x, p3.y);
            *reinterpret_cast<float4*>(&Y[row * 256 + colOff + c0])     = o0;
            *reinterpret_cast<float4*>(&Y[row * 256 + colOff + c0 + 4]) = o1;
        }
    }
}

// ---------------- combine: h_out[i] = relu(inv_deg[i]*sum_{src in CSR[i]} yl[src] + yr[i] + b) ----------------
// warp per node; mode 1 => fused global-mean-pool atomic accumulation instead of store
__global__ __launch_bounds__(256)
void combine_kernel(const float* __restrict__ Y, const float* __restrict__ bias,
                    float* __restrict__ Hout,
                    const int* __restrict__ batch, float* __restrict__ pooled,
                    int do_pool) {
    int i = (blockIdx.x * blockDim.x + threadIdx.x) >> 5;
    if (i >= N_NODES) return;
    int lane = threadIdx.x & 31;
    int e0 = g_row_start[i], e1 = g_row_start[i + 1];
    float4 acc0 = make_float4(0, 0, 0, 0), acc1 = make_float4(0, 0, 0, 0);
    int e = e0;
    for (; e + 2 <= e1; e += 2) {
        int sa = g_csr_src[e], sb = g_csr_src[e + 1];
        float4 va = *reinterpret_cast<const float4*>(&Y[sa * 256 + lane * 4]);
        float4 vb = *reinterpret_cast<const float4*>(&Y[sb * 256 + lane * 4]);
        acc0.x += va.x; acc0.y += va.y; acc0.z += va.z; acc0.w += va.w;
        acc1.x += vb.x; acc1.y += vb.y; acc1.z += vb.z; acc1.w += vb.w;
    }
    if (e < e1) {
        int sa = g_csr_src[e];
        float4 va = *reinterpret_cast<const float4*>(&Y[sa * 256 + lane * 4]);
        acc0.x += va.x; acc0.y += va.y; acc0.z += va.z; acc0.w += va.w;
    }
    float inv = g_inv_deg[i];
    float4 yr = *reinterpret_cast<const float4*>(&Y[i * 256 + 128 + lane * 4]);
    float4 bb = *reinterpret_cast<const float4*>(&bias[lane * 4]);
    float4 r;
    r.x = fmaxf(fmaf(acc0.x + acc1.x, inv, yr.x + bb.x), 0.0f);
    r.y = fmaxf(fmaf(acc0.y + acc1.y, inv, yr.y + bb.y), 0.0f);
    r.z = fmaxf(fmaf(acc0.z + acc1.z, inv, yr.z + bb.z), 0.0f);
    r.w = fmaxf(fmaf(acc0.w + acc1.w, inv, yr.w + bb.w), 0.0f);
    if (!do_pool) {
        *reinterpret_cast<float4*>(&Hout[i * HID + lane * 4]) = r;
    } else {
        int g = batch[i];
        float* p = &pooled[g * HID + lane * 4];
        atomicAdd(p + 0, r.x);
        atomicAdd(p + 1, r.y);
        atomicAdd(p + 2, r.z);
        atomicAdd(p + 3, r.w);
    }
}

// ---------------- final divide by per-graph counts ----------------
__global__ void div_kernel(float* __restrict__ pooled) {
    int idx = blockIdx.x * blockDim.x + threadIdx.x;
    if (idx < N_GRAPHS * HID) {
        int g = idx >> 7;
        pooled[idx] *= 1.0f / fmaxf((float)g_counts[g], 1.0f);
    }
}

// ---------------- launch ----------------
extern "C" void kernel_launch(void* const* d_in, const int* in_sizes, int n_in,
                              void* d_out, int out_size) {
    const float* x     = (const float*)d_in[0];
    const int*   ei    = (const int*)d_in[1];    // int32! (jax x64 disabled)
    const int*   batch = (const int*)d_in[2];    // int32!
    const float* W1l = (const float*)d_in[3];
    const float* W1r = (const float*)d_in[4];
    const float* b1  = (const float*)d_in[5];
    const float* W2l = (const float*)d_in[6];
    const float* W2r = (const float*)d_in[7];
    const float* b2  = (const float*)d_in[8];
    const float* W3l = (const float*)d_in[9];
    const float* W3r = (const float*)d_in[10];
    const float* b3  = (const float*)d_in[11];
    float* pooled = (float*)d_out;

    float *y, *h0, *h1;
    cudaGetSymbolAddress((void**)&y,  g_y);
    cudaGetSymbolAddress((void**)&h0, g_h0);
    cudaGetSymbolAddress((void**)&h1, g_h1);

    const int smem_gemm = (128 * 132 + 2 * 8 * 132) * (int)sizeof(float);
    cudaFuncSetAttribute(gemm_kernel, cudaFuncAttributeMaxDynamicSharedMemorySize, smem_gemm);

    init_kernel<<<256, 256>>>(pooled);
    hist_kernel<<<(N_EDGES + 255) / 256, 256>>>(ei, batch);
    scan_kernel<<<1, 1024>>>();
    csr_kernel<<<(N_EDGES + 255) / 256, 256>>>(ei);

    dim3 gg((N_NODES + 127) / 128, 2);

    // layer 1
    gemm_kernel<<<gg, 256, smem_gemm>>>(x, W1l, W1r, y);
    combine_kernel<<<N_NODES / 8, 256>>>(y, b1, h0, nullptr, nullptr, 0);
    // layer 2
    gemm_kernel<<<gg, 256, smem_gemm>>>(h0, W2l, W2r, y);
    combine_kernel<<<N_NODES / 8, 256>>>(y, b2, h1, nullptr, nullptr, 0);
    // layer 3 (pool fused)
    gemm_kernel<<<gg, 256, smem_gemm>>>(h1, W3l, W3r, y);
    combine_kernel<<<N_NODES / 8, 256>>>(y, b3, nullptr, batch, pooled, 1);

    div_kernel<<<(N_GRAPHS * HID + 255) / 256, 256>>>(pooled);
}

// round 5
// speedup vs baseline: 1.6910x; 1.6910x over previous
#include <cuda_runtime.h>
#include <cuda_bf16.h>
#include <cstdint>

#define N_NODES  50000
#define N_EDGES  800000
#define HID      128
#define N_GRAPHS 512

// ---------------- scratch ----------------
__device__ int   g_deg[N_NODES];
__device__ int   g_cursor[N_NODES];
__device__ int   g_row_start[N_NODES + 1];
__device__ int   g_counts[N_GRAPHS];
__device__ int   g_csr_src[N_EDGES];
__device__ float g_inv_deg[N_NODES];
__device__ float g_y[(size_t)N_NODES * 256];   // [node][0:128)=h@Wl^T, [128:256)=h@Wr^T

// bf16 hi/lo activation buffers (split precision)
__device__ __nv_bfloat16 g_xhi[(size_t)N_NODES * HID];
__device__ __nv_bfloat16 g_xlo[(size_t)N_NODES * HID];
__device__ __nv_bfloat16 g_hhi0[(size_t)N_NODES * HID];
__device__ __nv_bfloat16 g_hlo0[(size_t)N_NODES * HID];
__device__ __nv_bfloat16 g_hhi1[(size_t)N_NODES * HID];
__device__ __nv_bfloat16 g_hlo1[(size_t)N_NODES * HID];
// converted weights: [layer][256 rows (Wl then Wr)][128 k]
__device__ __nv_bfloat16 g_whi[3 * 256 * 128];
__device__ __nv_bfloat16 g_wlo[3 * 256 * 128];

// ---------------- init ----------------
__global__ void init_kernel(float* __restrict__ pooled) {
    int i = blockIdx.x * blockDim.x + threadIdx.x;
    int stride = gridDim.x * blockDim.x;
    for (int j = i; j < N_NODES; j += stride) g_deg[j] = 0;
    for (int j = i; j < N_GRAPHS; j += stride) g_counts[j] = 0;
    for (int j = i; j < N_GRAPHS * HID; j += stride) pooled[j] = 0.0f;
}

// ---------------- histograms ----------------
__global__ void hist_kernel(const int* __restrict__ ei, const int* __restrict__ batch) {
    int e = blockIdx.x * blockDim.x + threadIdx.x;
    if (e < N_EDGES) atomicAdd(&g_deg[ei[N_EDGES + e]], 1);
    if (e < N_NODES) atomicAdd(&g_counts[batch[e]], 1);
}

// ---------------- scan ----------------
__global__ void scan_kernel() {
    __shared__ int warp_sums[32];
    __shared__ int s_carry;
    const int t = threadIdx.x;
    const int lane = t & 31, wid = t >> 5;
    if (t == 0) s_carry = 0;
    __syncthreads();
    for (int base = 0; base < N_NODES; base += 1024) {
        int i = base + t;
        int v = (i < N_NODES) ? g_deg[i] : 0;
        int x = v;
#pragma unroll
        for (int o = 1; o < 32; o <<= 1) {
            int y = __shfl_up_sync(0xffffffffu, x, o);
            if (lane >= o) x += y;
        }
        if (lane == 31) warp_sums[wid] = x;
        __syncthreads();
        if (wid == 0) {
            int w = warp_sums[lane];
#pragma unroll
            for (int o = 1; o < 32; o <<= 1) {
                int y = __shfl_up_sync(0xffffffffu, w, o);
                if (lane >= o) w += y;
            }
            warp_sums[lane] = w;
        }
        __syncthreads();
        int prefix = s_carry + (wid ? warp_sums[wid - 1] : 0) + (x - v);
        if (i < N_NODES) {
            g_row_start[i] = prefix;
            g_cursor[i]    = prefix;
            g_inv_deg[i]   = 1.0f / fmaxf((float)v, 1.0f);
        }
        __syncthreads();
        if (t == 0) s_carry += warp_sums[31];
        __syncthreads();
    }
    if (t == 0) g_row_start[N_NODES] = s_carry;
}

// ---------------- CSR fill ----------------
__global__ void csr_kernel(const int* __restrict__ ei) {
    int e = blockIdx.x * blockDim.x + threadIdx.x;
    if (e >= N_EDGES) return;
    int d = ei[N_EDGES + e];
    int p = atomicAdd(&g_cursor[d], 1);
    g_csr_src[p] = ei[e];
}

// ---------------- split helpers ----------------
__device__ __forceinline__ void split1(float v, __nv_bfloat16& hi, __nv_bfloat16& lo) {
    hi = __float2bfloat16_rn(v);
    lo = __float2bfloat16_rn(v - __bfloat162float(hi));
}

// ---------------- convert x -> bf16 hi/lo ----------------
__global__ void xconv_kernel(const float* __restrict__ x) {
    int i = blockIdx.x * blockDim.x + threadIdx.x;   // one float4 per thread
    if (i >= N_NODES * HID / 4) return;
    float4 v = *reinterpret_cast<const float4*>(&x[i * 4]);
    __nv_bfloat16 h0, h1, h2, h3, l0, l1, l2, l3;
    split1(v.x, h0, l0); split1(v.y, h1, l1); split1(v.z, h2, l2); split1(v.w, h3, l3);
    __nv_bfloat16* ph = &g_xhi[i * 4];
    __nv_bfloat16* pl = &g_xlo[i * 4];
    ph[0] = h0; ph[1] = h1; ph[2] = h2; ph[3] = h3;
    pl[0] = l0; pl[1] = l1; pl[2] = l2; pl[3] = l3;
}

// ---------------- convert weights -> bf16 hi/lo : [layer][256][128] ----------------
__global__ void wconv_kernel(const float* __restrict__ W1l, const float* __restrict__ W1r,
                             const float* __restrict__ W2l, const float* __restrict__ W2r,
                             const float* __restrict__ W3l, const float* __restrict__ W3r) {
    int idx = blockIdx.x * blockDim.x + threadIdx.x;
    if (idx >= 3 * 256 * 128) return;
    int layer = idx / (256 * 128);
    int rem = idx % (256 * 128);
    int n = rem / 128, k = rem % 128;
    const float* Wp;
    if (layer == 0) Wp = (n < 128) ? W1l : W1r;
    else if (layer == 1) Wp = (n < 128) ? W2l : W2r;
    else Wp = (n < 128) ? W3l : W3r;
    float v = Wp[(n & 127) * 128 + k];
    __nv_bfloat16 hi, lo;
    split1(v, hi, lo);
    g_whi[idx] = hi;
    g_wlo[idx] = lo;
}

// ---------------- mma.sync bf16 GEMM: Y[128 x 256] = A @ [Wl^T | Wr^T] ----------------
// bf16x2 split: D = Ahi@Bhi + Ahi@Blo + Alo@Bhi (fp32 accum)
#define ASTR 136                       // smem row stride in bf16 elems (conflict-free)
static const int SM_AHI = 0;
static const int SM_ALO = SM_AHI + 128 * ASTR * 2;   // 34816
static const int SM_BHI = SM_ALO + 128 * ASTR * 2;   // 69632
static const int SM_BLO = SM_BHI + 256 * ASTR * 2;   // 139264
static const int SM_TOT = SM_BLO + 256 * ASTR * 2;   // 208896

__device__ __forceinline__ void mma16816(float* c, const uint32_t* a, const uint32_t* b) {
    asm volatile(
        "mma.sync.aligned.m16n8k16.row.col.f32.bf16.bf16.f32 "
        "{%0,%1,%2,%3}, {%4,%5,%6,%7}, {%8,%9}, {%0,%1,%2,%3};"
        : "+f"(c[0]), "+f"(c[1]), "+f"(c[2]), "+f"(c[3])
        : "r"(a[0]), "r"(a[1]), "r"(a[2]), "r"(a[3]), "r"(b[0]), "r"(b[1]));
}

__global__ __launch_bounds__(256, 1)
void gemm_tc_kernel(const __nv_bfloat16* __restrict__ Ahi, const __nv_bfloat16* __restrict__ Alo,
                    const __nv_bfloat16* __restrict__ Whi, const __nv_bfloat16* __restrict__ Wlo,
                    float* __restrict__ Y) {
    extern __shared__ char smem[];
    const int t = threadIdx.x;
    const int row0 = blockIdx.x * 128;

    // ---- stage A (128x128 bf16 hi/lo) ----
#pragma unroll
    for (int i = t; i < 128 * 16; i += 256) {
        int r = i >> 4, k = (i & 15) * 8;
        int row = row0 + r;
        uint4 vh = make_uint4(0, 0, 0, 0), vl = make_uint4(0, 0, 0, 0);
        if (row < N_NODES) {
            vh = *reinterpret_cast<const uint4*>(&Ahi[(size_t)row * HID + k]);
            vl = *reinterpret_cast<const uint4*>(&Alo[(size_t)row * HID + k]);
        }
        *reinterpret_cast<uint4*>(smem + SM_AHI + (r * ASTR + k) * 2) = vh;
        *reinterpret_cast<uint4*>(smem + SM_ALO + (r * ASTR + k) * 2) = vl;
    }
    // ---- stage B (256x128 bf16 hi/lo) ----
#pragma unroll
    for (int i = t; i < 256 * 16; i += 256) {
        int n = i >> 4, k = (i & 15) * 8;
        *reinterpret_cast<uint4*>(smem + SM_BHI + (n * ASTR + k) * 2) =
            *reinterpret_cast<const uint4*>(&Whi[n * HID + k]);
        *reinterpret_cast<uint4*>(smem + SM_BLO + (n * ASTR + k) * 2) =
            *reinterpret_cast<const uint4*>(&Wlo[n * HID + k]);
    }
    __syncthreads();

    const int wid = t >> 5, lane = t & 31;
    const int g = lane >> 2, tig = lane & 3;
    const int wm = (wid & 1) * 64;        // warp M offset (2 warps in M)
    const int wn = (wid >> 1) * 64;       // warp N offset (4 warps in N)

    float acc[4][8][4];
#pragma unroll
    for (int a = 0; a < 4; a++)
#pragma unroll
        for (int b = 0; b < 8; b++)
#pragma unroll
            for (int c = 0; c < 4; c++) acc[a][b][c] = 0.0f;

    for (int ks = 0; ks < 8; ks++) {
        const int k0 = ks * 16 + tig * 2;
        uint32_t ah[4][4], al[4][4];
#pragma unroll
        for (int mt = 0; mt < 4; mt++) {
            int base = ((wm + mt * 16 + g) * ASTR + k0) * 2;
            ah[mt][0] = *reinterpret_cast<const uint32_t*>(smem + SM_AHI + base);
            ah[mt][1] = *reinterpret_cast<const uint32_t*>(smem + SM_AHI + base + 8 * ASTR * 2);
            ah[mt][2] = *reinterpret_cast<const uint32_t*>(smem + SM_AHI + base + 16);
            ah[mt][3] = *reinterpret_cast<const uint32_t*>(smem + SM_AHI + base + 8 * ASTR * 2 + 16);
            al[mt][0] = *reinterpret_cast<const uint32_t*>(smem + SM_ALO + base);
            al[mt][1] = *reinterpret_cast<const uint32_t*>(smem + SM_ALO + base + 8 * ASTR * 2);
            al[mt][2] = *reinterpret_cast<const uint32_t*>(smem + SM_ALO + base + 16);
            al[mt][3] = *reinterpret_cast<const uint32_t*>(smem + SM_ALO + base + 8 * ASTR * 2 + 16);
        }
#pragma unroll
        for (int nh = 0; nh < 2; nh++) {
            uint32_t bh[4][2], bl[4][2];
#pragma unroll
            for (int nt = 0; nt < 4; nt++) {
                int base = ((wn + nh * 32 + nt * 8 + g) * ASTR + k0) * 2;
                bh[nt][0] = *reinterpret_cast<const uint32_t*>(smem + SM_BHI + base);
                bh[nt][1] = *reinterpret_cast<const uint32_t*>(smem + SM_BHI + base + 16);
                bl[nt][0] = *reinterpret_cast<const uint32_t*>(smem + SM_BLO + base);
                bl[nt][1] = *reinterpret_cast<const uint32_t*>(smem + SM_BLO + base + 16);
            }
#pragma unroll
            for (int mt = 0; mt < 4; mt++)
#pragma unroll
                for (int nt = 0; nt < 4; nt++) {
                    float* c = acc[mt][nh * 4 + nt];
                    mma16816(c, ah[mt], bh[nt]);
                    mma16816(c, ah[mt], bl[nt]);
                    mma16816(c, al[mt], bh[nt]);
                }
        }
    }

    // ---- epilogue: write fp32 Y ----
#pragma unroll
    for (int mt = 0; mt < 4; mt++)
#pragma unroll
        for (int nt = 0; nt < 8; nt++) {
            int row = row0 + wm + mt * 16 + g;
            int col = wn + nt * 8 + tig * 2;
            float* c = acc[mt][nt];
            if (row < N_NODES)
                *reinterpret_cast<float2*>(&Y[(size_t)row * 256 + col]) = make_float2(c[0], c[1]);
            if (row + 8 < N_NODES)
                *reinterpret_cast<float2*>(&Y[(size_t)(row + 8) * 256 + col]) = make_float2(c[2], c[3]);
        }
}

// ---------------- combine: relu(inv_deg*sum yl[src] + yr + b) -> bf16 hi/lo (or pooled atomics) ----------------
__global__ __launch_bounds__(256)
void combine_kernel(const float* __restrict__ Y, const float* __restrict__ bias,
                    __nv_bfloat16* __restrict__ Hhi, __nv_bfloat16* __restrict__ Hlo,
                    const int* __restrict__ batch, float* __restrict__ pooled,
                    int do_pool) {
    int i = (blockIdx.x * blockDim.x + threadIdx.x) >> 5;
    if (i >= N_NODES) return;
    int lane = threadIdx.x & 31;
    int e0 = g_row_start[i], e1 = g_row_start[i + 1];
    float4 acc0 = make_float4(0, 0, 0, 0), acc1 = make_float4(0, 0, 0, 0);
    int e = e0;
    for (; e + 2 <= e1; e += 2) {
        int sa = g_csr_src[e], sb2 = g_csr_src[e + 1];
        float4 va = *reinterpret_cast<const float4*>(&Y[(size_t)sa * 256 + lane * 4]);
        float4 vb = *reinterpret_cast<const float4*>(&Y[(size_t)sb2 * 256 + lane * 4]);
        acc0.x += va.x; acc0.y += va.y; acc0.z += va.z; acc0.w += va.w;
        acc1.x += vb.x; acc1.y += vb.y; acc1.z += vb.z; acc1.w += vb.w;
    }
    if (e < e1) {
        int sa = g_csr_src[e];
        float4 va = *reinterpret_cast<const float4*>(&Y[(size_t)sa * 256 + lane * 4]);
        acc0.x += va.x; acc0.y += va.y; acc0.z += va.z; acc0.w += va.w;
    }
    float inv = g_inv_deg[i];
    float4 yr = *reinterpret_cast<const float4*>(&Y[(size_t)i * 256 + 128 + lane * 4]);
    float4 bb = *reinterpret_cast<const float4*>(&bias[lane * 4]);
    float4 r;
    r.x = fmaxf(fmaf(acc0.x + acc1.x, inv, yr.x + bb.x), 0.0f);
    r.y = fmaxf(fmaf(acc0.y + acc1.y, inv, yr.y + bb.y), 0.0f);
    r.z = fmaxf(fmaf(acc0.z + acc1.z, inv, yr.z + bb.z), 0.0f);
    r.w = fmaxf(fmaf(acc0.w + acc1.w, inv, yr.w + bb.w), 0.0f);
    if (!do_pool) {
        __nv_bfloat16 h0, h1, h2, h3, l0, l1, l2, l3;
        split1(r.x, h0, l0); split1(r.y, h1, l1); split1(r.z, h2, l2); split1(r.w, h3, l3);
        __nv_bfloat16* ph = &Hhi[(size_t)i * HID + lane * 4];
        __nv_bfloat16* pl = &Hlo[(size_t)i * HID + lane * 4];
        ph[0] = h0; ph[1] = h1; ph[2] = h2; ph[3] = h3;
        pl[0] = l0; pl[1] = l1; pl[2] = l2; pl[3] = l3;
    } else {
        int g = batch[i];
        float* p = &pooled[(size_t)g * HID + lane * 4];
        atomicAdd(p + 0, r.x);
        atomicAdd(p + 1, r.y);
        atomicAdd(p + 2, r.z);
        atomicAdd(p + 3, r.w);
    }
}

// ---------------- final divide ----------------
__global__ void div_kernel(float* __restrict__ pooled) {
    int idx = blockIdx.x * blockDim.x + threadIdx.x;
    if (idx < N_GRAPHS * HID) {
        int g = idx >> 7;
        pooled[idx] *= 1.0f / fmaxf((float)g_counts[g], 1.0f);
    }
}

// ---------------- launch ----------------
extern "C" void kernel_launch(void* const* d_in, const int* in_sizes, int n_in,
                              void* d_out, int out_size) {
    const float* x     = (const float*)d_in[0];
    const int*   ei    = (const int*)d_in[1];
    const int*   batch = (const int*)d_in[2];
    const float* W1l = (const float*)d_in[3];
    const float* W1r = (const float*)d_in[4];
    const float* b1  = (const float*)d_in[5];
    const float* W2l = (const float*)d_in[6];
    const float* W2r = (const float*)d_in[7];
    const float* b2  = (const float*)d_in[8];
    const float* W3l = (const float*)d_in[9];
    const float* W3r = (const float*)d_in[10];
    const float* b3  = (const float*)d_in[11];
    float* pooled = (float*)d_out;

    float* y;
    __nv_bfloat16 *xhi, *xlo, *hhi0, *hlo0, *hhi1, *hlo1, *whi, *wlo;
    cudaGetSymbolAddress((void**)&y,    g_y);
    cudaGetSymbolAddress((void**)&xhi,  g_xhi);
    cudaGetSymbolAddress((void**)&xlo,  g_xlo);
    cudaGetSymbolAddress((void**)&hhi0, g_hhi0);
    cudaGetSymbolAddress((void**)&hlo0, g_hlo0);
    cudaGetSymbolAddress((void**)&hhi1, g_hhi1);
    cudaGetSymbolAddress((void**)&hlo1, g_hlo1);
    cudaGetSymbolAddress((void**)&whi,  g_whi);
    cudaGetSymbolAddress((void**)&wlo,  g_wlo);

    cudaFuncSetAttribute(gemm_tc_kernel, cudaFuncAttributeMaxDynamicSharedMemorySize, SM_TOT);

    init_kernel<<<256, 256>>>(pooled);
    hist_kernel<<<(N_EDGES + 255) / 256, 256>>>(ei, batch);
    scan_kernel<<<1, 1024>>>();
    csr_kernel<<<(N_EDGES + 255) / 256, 256>>>(ei);
    xconv_kernel<<<(N_NODES * HID / 4 + 255) / 256, 256>>>(x);
    wconv_kernel<<<(3 * 256 * 128 + 255) / 256, 256>>>(W1l, W1r, W2l, W2r, W3l, W3r);

    const int ntiles = (N_NODES + 127) / 128;

    // layer 1
    gemm_tc_kernel<<<ntiles, 256, SM_TOT>>>(xhi, xlo, whi, wlo, y);
    combine_kernel<<<N_NODES / 8, 256>>>(y, b1, hhi0, hlo0, nullptr, nullptr, 0);
    // layer 2
    gemm_tc_kernel<<<ntiles, 256, SM_TOT>>>(hhi0, hlo0, whi + 256 * 128, wlo + 256 * 128, y);
    combine_kernel<<<N_NODES / 8, 256>>>(y, b2, hhi1, hlo1, nullptr, nullptr, 0);
    // layer 3 (pool fused)
    gemm_tc_kernel<<<ntiles, 256, SM_TOT>>>(hhi1, hlo1, whi + 2 * 256 * 128, wlo + 2 * 256 * 128, y);
    combine_kernel<<<N_NODES / 8, 256>>>(y, b3, nullptr, nullptr, batch, pooled, 1);

    div_kernel<<<(N_GRAPHS * HID + 255) / 256, 256>>>(pooled);
}

// round 6
// speedup vs baseline: 1.9411x; 1.1479x over previous
#include <cuda_runtime.h>
#include <cuda_bf16.h>
#include <cuda_fp16.h>
#include <cstdint>

#define N_NODES  50000
#define N_EDGES  800000
#define HID      128
#define N_GRAPHS 512

// ---------------- scratch ----------------
__device__ int   g_deg[N_NODES];
__device__ int   g_tmp_incl[N_NODES];
__device__ int   g_bsum[64];
__device__ int   g_boff[64];
__device__ int   g_cursor[N_NODES];
__device__ int   g_row_start[N_NODES + 1];
__device__ int   g_counts[N_GRAPHS];
__device__ int   g_csr_src[N_EDGES];
__device__ float g_inv_deg[N_NODES];

__device__ __half g_ylh[(size_t)N_NODES * 128];   // left-branch product, fp16 (gathered)
__device__ float  g_yr[(size_t)N_NODES * 128];    // right-branch product, fp32 (own row)

// bf16 hi/lo activation buffers (split precision)
__device__ __nv_bfloat16 g_xhi[(size_t)N_NODES * HID];
__device__ __nv_bfloat16 g_xlo[(size_t)N_NODES * HID];
__device__ __nv_bfloat16 g_hhi0[(size_t)N_NODES * HID];
__device__ __nv_bfloat16 g_hlo0[(size_t)N_NODES * HID];
__device__ __nv_bfloat16 g_hhi1[(size_t)N_NODES * HID];
__device__ __nv_bfloat16 g_hlo1[(size_t)N_NODES * HID];
// converted weights: [layer][256 rows (Wl then Wr)][128 k]
__device__ __nv_bfloat16 g_whi[3 * 256 * 128];
__device__ __nv_bfloat16 g_wlo[3 * 256 * 128];

// ---------------- init ----------------
__global__ void init_kernel(float* __restrict__ pooled) {
    int i = blockIdx.x * blockDim.x + threadIdx.x;
    int stride = gridDim.x * blockDim.x;
    for (int j = i; j < N_NODES; j += stride) g_deg[j] = 0;
    for (int j = i; j < N_GRAPHS; j += stride) g_counts[j] = 0;
    for (int j = i; j < N_GRAPHS * HID; j += stride) pooled[j] = 0.0f;
}

// ---------------- histograms ----------------
__global__ void hist_kernel(const int* __restrict__ ei, const int* __restrict__ batch) {
    int e = blockIdx.x * blockDim.x + threadIdx.x;
    if (e < N_EDGES) atomicAdd(&g_deg[ei[N_EDGES + e]], 1);
    if (e < N_NODES) atomicAdd(&g_counts[batch[e]], 1);
}

// ---------------- multi-block scan: A (block inclusive scans) ----------------
__global__ __launch_bounds__(1024)
void scanA_kernel() {
    __shared__ int wsum[32];
    const int t = threadIdx.x, lane = t & 31, wid = t >> 5;
    const int i = blockIdx.x * 1024 + t;
    int v = (i < N_NODES) ? g_deg[i] : 0;
    int x = v;
#pragma unroll
    for (int o = 1; o < 32; o <<= 1) {
        int y = __shfl_up_sync(0xffffffffu, x, o);
        if (lane >= o) x += y;
    }
    if (lane == 31) wsum[wid] = x;
    __syncthreads();
    if (wid == 0) {
        int w = wsum[lane];
#pragma unroll
        for (int o = 1; o < 32; o <<= 1) {
            int y = __shfl_up_sync(0xffffffffu, w, o);
            if (lane >= o) w += y;
        }
        wsum[lane] = w;
    }
    __syncthreads();
    int incl = x + (wid ? wsum[wid - 1] : 0);
    if (i < N_NODES) g_tmp_incl[i] = incl;
    if (t == 1023) g_bsum[blockIdx.x] = incl;
}

// ---------------- scan B: exclusive scan of 49 block sums ----------------
__global__ void scanB_kernel(int nblocks) {
    __shared__ int s[64];
    int t = threadIdx.x;
    s[t] = (t < nblocks) ? g_bsum[t] : 0;
    __syncthreads();
    if (t == 0) {
        int acc = 0;
#pragma unroll
        for (int k = 0; k < 64; k++) { int v = s[k]; s[k] = acc; acc += v; }
        g_row_start[N_NODES] = acc;
    }
    __syncthreads();
    g_boff[t] = s[t];
}

// ---------------- scan C: finalize row_start / cursor / inv_deg ----------------
__global__ __launch_bounds__(1024)
void scanC_kernel() {
    const int i = blockIdx.x * 1024 + threadIdx.x;
    if (i >= N_NODES) return;
    int d = g_deg[i];
    int rs = g_boff[blockIdx.x] + g_tmp_incl[i] - d;
    g_row_start[i] = rs;
    g_cursor[i]    = rs;
    g_inv_deg[i]   = 1.0f / fmaxf((float)d, 1.0f);
}

// ---------------- CSR fill ----------------
__global__ void csr_kernel(const int* __restrict__ ei) {
    int e = blockIdx.x * blockDim.x + threadIdx.x;
    if (e >= N_EDGES) return;
    int d = ei[N_EDGES + e];
    int p = atomicAdd(&g_cursor[d], 1);
    g_csr_src[p] = ei[e];
}

// ---------------- split helpers ----------------
__device__ __forceinline__ void split1(float v, __nv_bfloat16& hi, __nv_bfloat16& lo) {
    hi = __float2bfloat16_rn(v);
    lo = __float2bfloat16_rn(v - __bfloat162float(hi));
}

// ---------------- convert x and weights -> bf16 hi/lo (merged) ----------------
__global__ void conv_kernel(const float* __restrict__ x,
                            const float* __restrict__ W1l, const float* __restrict__ W1r,
                            const float* __restrict__ W2l, const float* __restrict__ W2r,
                            const float* __restrict__ W3l, const float* __restrict__ W3r) {
    int i = blockIdx.x * blockDim.x + threadIdx.x;   // one float4 of x per thread
    if (i < N_NODES * HID / 4) {
        float4 v = *reinterpret_cast<const float4*>(&x[(size_t)i * 4]);
        __nv_bfloat16 h0, h1, h2, h3, l0, l1, l2, l3;
        split1(v.x, h0, l0); split1(v.y, h1, l1); split1(v.z, h2, l2); split1(v.w, h3, l3);
        __nv_bfloat16* ph = &g_xhi[(size_t)i * 4];
        __nv_bfloat16* pl = &g_xlo[(size_t)i * 4];
        ph[0] = h0; ph[1] = h1; ph[2] = h2; ph[3] = h3;
        pl[0] = l0; pl[1] = l1; pl[2] = l2; pl[3] = l3;
    }
    if (i < 3 * 256 * 128) {
        int layer = i / (256 * 128);
        int rem = i % (256 * 128);
        int n = rem / 128, k = rem % 128;
        const float* Wp;
        if (layer == 0) Wp = (n < 128) ? W1l : W1r;
        else if (layer == 1) Wp = (n < 128) ? W2l : W2r;
        else Wp = (n < 128) ? W3l : W3r;
        float v = Wp[(n & 127) * 128 + k];
        __nv_bfloat16 hi, lo;
        split1(v, hi, lo);
        g_whi[i] = hi;
        g_wlo[i] = lo;
    }
}

// ---------------- mma.sync bf16 GEMM: [yl(fp16) | yr(fp32)] = A @ [Wl^T | Wr^T] ----------------
// bf16x2 split: D = Ahi@Bhi + Ahi@Blo + Alo@Bhi (fp32 accum)
#define ASTR 136                       // smem row stride in bf16 elems (conflict-free)
static const int SM_AHI = 0;
static const int SM_ALO = SM_AHI + 128 * ASTR * 2;   // 34816
static const int SM_BHI = SM_ALO + 128 * ASTR * 2;   // 69632
static const int SM_BLO = SM_BHI + 256 * ASTR * 2;   // 139264
static const int SM_TOT = SM_BLO + 256 * ASTR * 2;   // 208896

__device__ __forceinline__ void mma16816(float* c, const uint32_t* a, const uint32_t* b) {
    asm volatile(
        "mma.sync.aligned.m16n8k16.row.col.f32.bf16.bf16.f32 "
        "{%0,%1,%2,%3}, {%4,%5,%6,%7}, {%8,%9}, {%0,%1,%2,%3};"
        : "+f"(c[0]), "+f"(c[1]), "+f"(c[2]), "+f"(c[3])
        : "r"(a[0]), "r"(a[1]), "r"(a[2]), "r"(a[3]), "r"(b[0]), "r"(b[1]));
}

__global__ __launch_bounds__(256, 1)
void gemm_tc_kernel(const __nv_bfloat16* __restrict__ Ahi, const __nv_bfloat16* __restrict__ Alo,
                    const __nv_bfloat16* __restrict__ Whi, const __nv_bfloat16* __restrict__ Wlo) {
    extern __shared__ char smem[];
    const int t = threadIdx.x;
    const int row0 = blockIdx.x * 128;

    // ---- stage A (128x128 bf16 hi/lo) ----
#pragma unroll
    for (int i = t; i < 128 * 16; i += 256) {
        int r = i >> 4, k = (i & 15) * 8;
        int row = row0 + r;
        uint4 vh = make_uint4(0, 0, 0, 0), vl = make_uint4(0, 0, 0, 0);
        if (row < N_NODES) {
            vh = *reinterpret_cast<const uint4*>(&Ahi[(size_t)row * HID + k]);
            vl = *reinterpret_cast<const uint4*>(&Alo[(size_t)row * HID + k]);
        }
        *reinterpret_cast<uint4*>(smem + SM_AHI + (r * ASTR + k) * 2) = vh;
        *reinterpret_cast<uint4*>(smem + SM_ALO + (r * ASTR + k) * 2) = vl;
    }
    // ---- stage B (256x128 bf16 hi/lo) ----
#pragma unroll
    for (int i = t; i < 256 * 16; i += 256) {
        int n = i >> 4, k = (i & 15) * 8;
        *reinterpret_cast<uint4*>(smem + SM_BHI + (n * ASTR + k) * 2) =
            *reinterpret_cast<const uint4*>(&Whi[n * HID + k]);
        *reinterpret_cast<uint4*>(smem + SM_BLO + (n * ASTR + k) * 2) =
            *reinterpret_cast<const uint4*>(&Wlo[n * HID + k]);
    }
    __syncthreads();

    const int wid = t >> 5, lane = t & 31;
    const int g = lane >> 2, tig = lane & 3;
    const int wm = (wid & 1) * 64;        // warp M offset (2 warps in M)
    const int wn = (wid >> 1) * 64;       // warp N offset (4 warps in N)

    float acc[4][8][4];
#pragma unroll
    for (int a = 0; a < 4; a++)
#pragma unroll
        for (int b = 0; b < 8; b++)
#pragma unroll
            for (int c = 0; c < 4; c++) acc[a][b][c] = 0.0f;

    for (int ks = 0; ks < 8; ks++) {
        const int k0 = ks * 16 + tig * 2;
        uint32_t ah[4][4], al[4][4];
#pragma unroll
        for (int mt = 0; mt < 4; mt++) {
            int base = ((wm + mt * 16 + g) * ASTR + k0) * 2;
            ah[mt][0] = *reinterpret_cast<const uint32_t*>(smem + SM_AHI + base);
            ah[mt][1] = *reinterpret_cast<const uint32_t*>(smem + SM_AHI + base + 8 * ASTR * 2);
            ah[mt][2] = *reinterpret_cast<const uint32_t*>(smem + SM_AHI + base + 16);
            ah[mt][3] = *reinterpret_cast<const uint32_t*>(smem + SM_AHI + base + 8 * ASTR * 2 + 16);
            al[mt][0] = *reinterpret_cast<const uint32_t*>(smem + SM_ALO + base);
            al[mt][1] = *reinterpret_cast<const uint32_t*>(smem + SM_ALO + base + 8 * ASTR * 2);
            al[mt][2] = *reinterpret_cast<const uint32_t*>(smem + SM_ALO + base + 16);
            al[mt][3] = *reinterpret_cast<const uint32_t*>(smem + SM_ALO + base + 8 * ASTR * 2 + 16);
        }
#pragma unroll
        for (int nh = 0; nh < 2; nh++) {
            uint32_t bh[4][2], bl[4][2];
#pragma unroll
            for (int nt = 0; nt < 4; nt++) {
                int base = ((wn + nh * 32 + nt * 8 + g) * ASTR + k0) * 2;
                bh[nt][0] = *reinterpret_cast<const uint32_t*>(smem + SM_BHI + base);
                bh[nt][1] = *reinterpret_cast<const uint32_t*>(smem + SM_BHI + base + 16);
                bl[nt][0] = *reinterpret_cast<const uint32_t*>(smem + SM_BLO + base);
                bl[nt][1] = *reinterpret_cast<const uint32_t*>(smem + SM_BLO + base + 16);
            }
#pragma unroll
            for (int mt = 0; mt < 4; mt++)
#pragma unroll
                for (int nt = 0; nt < 4; nt++) {
                    float* c = acc[mt][nh * 4 + nt];
                    mma16816(c, ah[mt], bh[nt]);
                    mma16816(c, ah[mt], bl[nt]);
                    mma16816(c, al[mt], bh[nt]);
                }
        }
    }

    // ---- epilogue: cols [0,128) -> fp16 g_ylh ; cols [128,256) -> fp32 g_yr ----
#pragma unroll
    for (int mt = 0; mt < 4; mt++)
#pragma unroll
        for (int nt = 0; nt < 8; nt++) {
            int row = row0 + wm + mt * 16 + g;
            int col = wn + nt * 8 + tig * 2;
            float* c = acc[mt][nt];
            if (col < 128) {
                if (row < N_NODES)
                    *reinterpret_cast<__half2*>(&g_ylh[(size_t)row * 128 + col]) =
                        __floats2half2_rn(c[0], c[1]);
                if (row + 8 < N_NODES)
                    *reinterpret_cast<__half2*>(&g_ylh[(size_t)(row + 8) * 128 + col]) =
                        __floats2half2_rn(c[2], c[3]);
            } else {
                int cr = col - 128;
                if (row < N_NODES)
                    *reinterpret_cast<float2*>(&g_yr[(size_t)row * 128 + cr]) = make_float2(c[0], c[1]);
                if (row + 8 < N_NODES)
                    *reinterpret_cast<float2*>(&g_yr[(size_t)(row + 8) * 128 + cr]) = make_float2(c[2], c[3]);
            }
        }
}

// ---------------- combine: relu(inv_deg*sum yl[src] + yr + b) -> bf16 hi/lo (or pooled atomics) ----------------
__device__ __forceinline__ void acc_half4(float4& acc, const __half* p) {
    uint2 u = *reinterpret_cast<const uint2*>(p);
    float2 f0 = __half22float2(*reinterpret_cast<__half2*>(&u.x));
    float2 f1 = __half22float2(*reinterpret_cast<__half2*>(&u.y));
    acc.x += f0.x; acc.y += f0.y; acc.z += f1.x; acc.w += f1.y;
}

__global__ __launch_bounds__(256)
void combine_kernel(const float* __restrict__ bias,
                    __nv_bfloat16* __restrict__ Hhi, __nv_bfloat16* __restrict__ Hlo,
                    const int* __restrict__ batch, float* __restrict__ pooled,
                    int do_pool) {
    int i = (blockIdx.x * blockDim.x + threadIdx.x) >> 5;
    if (i >= N_NODES) return;
    int lane = threadIdx.x & 31;
    int e0 = g_row_start[i], e1 = g_row_start[i + 1];
    float4 acc0 = make_float4(0, 0, 0, 0), acc1 = make_float4(0, 0, 0, 0);
    float4 acc2 = make_float4(0, 0, 0, 0), acc3 = make_float4(0, 0, 0, 0);
    int e = e0;
    const int lo4 = lane * 4;
    for (; e + 4 <= e1; e += 4) {
        int s0 = g_csr_src[e], s1 = g_csr_src[e + 1];
        int s2 = g_csr_src[e + 2], s3 = g_csr_src[e + 3];
        acc_half4(acc0, &g_ylh[(size_t)s0 * 128 + lo4]);
        acc_half4(acc1, &g_ylh[(size_t)s1 * 128 + lo4]);
        acc_half4(acc2, &g_ylh[(size_t)s2 * 128 + lo4]);
        acc_half4(acc3, &g_ylh[(size_t)s3 * 128 + lo4]);
    }
    for (; e < e1; e++) {
        int s0 = g_csr_src[e];
        acc_half4(acc0, &g_ylh[(size_t)s0 * 128 + lo4]);
    }
    acc0.x += acc1.x + acc2.x + acc3.x;
    acc0.y += acc1.y + acc2.y + acc3.y;
    acc0.z += acc1.z + acc2.z + acc3.z;
    acc0.w += acc1.w + acc2.w + acc3.w;

    float inv = g_inv_deg[i];
    float4 yr = *reinterpret_cast<const float4*>(&g_yr[(size_t)i * 128 + lo4]);
    float4 bb = *reinterpret_cast<const float4*>(&bias[lo4]);
    float4 r;
    r.x = fmaxf(fmaf(acc0.x, inv, yr.x + bb.x), 0.0f);
    r.y = fmaxf(fmaf(acc0.y, inv, yr.y + bb.y), 0.0f);
    r.z = fmaxf(fmaf(acc0.z, inv, yr.z + bb.z), 0.0f);
    r.w = fmaxf(fmaf(acc0.w, inv, yr.w + bb.w), 0.0f);
    if (!do_pool) {
        __nv_bfloat16 h0, h1, h2, h3, l0, l1, l2, l3;
        split1(r.x, h0, l0); split1(r.y, h1, l1); split1(r.z, h2, l2); split1(r.w, h3, l3);
        __nv_bfloat16* ph = &Hhi[(size_t)i * HID + lo4];
        __nv_bfloat16* pl = &Hlo[(size_t)i * HID + lo4];
        ph[0] = h0; ph[1] = h1; ph[2] = h2; ph[3] = h3;
        pl[0] = l0; pl[1] = l1; pl[2] = l2; pl[3] = l3;
    } else {
        int g = batch[i];
        float* p = &pooled[(size_t)g * HID + lo4];
        atomicAdd(p + 0, r.x);
        atomicAdd(p + 1, r.y);
        atomicAdd(p + 2, r.z);
        atomicAdd(p + 3, r.w);
    }
}

// ---------------- final divide ----------------
__global__ void div_kernel(float* __restrict__ pooled) {
    int idx = blockIdx.x * blockDim.x + threadIdx.x;
    if (idx < N_GRAPHS * HID) {
        int g = idx >> 7;
        pooled[idx] *= 1.0f / fmaxf((float)g_counts[g], 1.0f);
    }
}

// ---------------- launch ----------------
extern "C" void kernel_launch(void* const* d_in, const int* in_sizes, int n_in,
                              void* d_out, int out_size) {
    const float* x     = (const float*)d_in[0];
    const int*   ei    = (const int*)d_in[1];
    const int*   batch = (const int*)d_in[2];
    const float* W1l = (const float*)d_in[3];
    const float* W1r = (const float*)d_in[4];
    const float* b1  = (const float*)d_in[5];
    const float* W2l = (const float*)d_in[6];
    const float* W2r = (const float*)d_in[7];
    const float* b2  = (const float*)d_in[8];
    const float* W3l = (const float*)d_in[9];
    const float* W3r = (const float*)d_in[10];
    const float* b3  = (const float*)d_in[11];
    float* pooled = (float*)d_out;

    __nv_bfloat16 *xhi, *xlo, *hhi0, *hlo0, *hhi1, *hlo1, *whi, *wlo;
    cudaGetSymbolAddress((void**)&xhi,  g_xhi);
    cudaGetSymbolAddress((void**)&xlo,  g_xlo);
    cudaGetSymbolAddress((void**)&hhi0, g_hhi0);
    cudaGetSymbolAddress((void**)&hlo0, g_hlo0);
    cudaGetSymbolAddress((void**)&hhi1, g_hhi1);
    cudaGetSymbolAddress((void**)&hlo1, g_hlo1);
    cudaGetSymbolAddress((void**)&whi,  g_whi);
    cudaGetSymbolAddress((void**)&wlo,  g_wlo);

    cudaFuncSetAttribute(gemm_tc_kernel, cudaFuncAttributeMaxDynamicSharedMemorySize, SM_TOT);

    const int nscan = (N_NODES + 1023) / 1024;   // 49

    init_kernel<<<256, 256>>>(pooled);
    hist_kernel<<<(N_EDGES + 255) / 256, 256>>>(ei, batch);
    scanA_kernel<<<nscan, 1024>>>();
    scanB_kernel<<<1, 64>>>(nscan);
    scanC_kernel<<<nscan, 1024>>>();
    csr_kernel<<<(N_EDGES + 255) / 256, 256>>>(ei);
    conv_kernel<<<(N_NODES * HID / 4 + 255) / 256, 256>>>(x, W1l, W1r, W2l, W2r, W3l, W3r);

    const int ntiles = (N_NODES + 127) / 128;

    // layer 1
    gemm_tc_kernel<<<ntiles, 256, SM_TOT>>>(xhi, xlo, whi, wlo);
    combine_kernel<<<N_NODES / 8, 256>>>(b1, hhi0, hlo0, nullptr, nullptr, 0);
    // layer 2
    gemm_tc_kernel<<<ntiles, 256, SM_TOT>>>(hhi0, hlo0, whi + 256 * 128, wlo + 256 * 128);
    combine_kernel<<<N_NODES / 8, 256>>>(b2, hhi1, hlo1, nullptr, nullptr, 0);
    // layer 3 (pool fused)
    gemm_tc_kernel<<<ntiles, 256, SM_TOT>>>(hhi1, hlo1, whi + 2 * 256 * 128, wlo + 2 * 256 * 128);
    combine_kernel<<<N_NODES / 8, 256>>>(b3, nullptr, nullptr, batch, pooled, 1);

    div_kernel<<<(N_GRAPHS * HID + 255) / 256, 256>>>(pooled);
}